// round 8
// baseline (speedup 1.0000x reference)
#include <cuda_runtime.h>
#include <cuda_bf16.h>

// CustomEmbedding: out[t, :] = sin((id/1000)*(i+1)) if id<1000 else weight[id, :]
// Tokens: 8*4096 = 32768, DIM = 512 floats = 128 float4 per row.
//
// PERSISTENT version: grid = 148*4 = 592 blocks (all resident, one wave).
// Each WARP grid-strides over tokens, one token per iteration:
//   - next token's id is prefetched BEFORE processing the current one,
//     hiding the id-load latency behind the row loads/stores
//   - 4 independent row LDG.128s per iteration (proven R6 shape, ~40 regs)
//   - 4 streaming STG.128s (evict-first keeps the weight table L2-resident)

#define DIM4 128            // 512 floats / 4
#define GRID_BLOCKS (148 * 4)
#define BLK_THREADS 256

__device__ __forceinline__ float4 sin4(float s, int jj) {
    float b = (float)(jj * 4);
    float4 v;
    v.x = sinf(s * (b + 1.0f));
    v.y = sinf(s * (b + 2.0f));
    v.z = sinf(s * (b + 3.0f));
    v.w = sinf(s * (b + 4.0f));
    return v;
}

__global__ void __launch_bounds__(BLK_THREADS)
embed_kernel(const int* __restrict__ x,     // token ids
             const float4* __restrict__ w,  // [VOCAB, DIM4]
             float4* __restrict__ out,      // [N, DIM4]
             int n_tokens)
{
    const int warp   = (blockIdx.x * BLK_THREADS + threadIdx.x) >> 5;
    const int j      = threadIdx.x & 31;                 // lane -> float4 idx base
    const int stride = (GRID_BLOCKS * BLK_THREADS) >> 5; // total warps = 4736

    int t = warp;
    if (t >= n_tokens) return;

    int id_cur = __ldg(x + t);                           // prime the pipeline

    while (true) {
        const int t_next = t + stride;
        int id_next = 0;
        if (t_next < n_tokens)
            id_next = __ldg(x + t_next);                 // prefetch next id early

        const int id = id_cur;
        float4 v0, v1, v2, v3;

        if (id >= 1000) {
            const float4* r = w + (size_t)id * DIM4;
            v0 = __ldg(r + j);
            v1 = __ldg(r + j + 32);
            v2 = __ldg(r + j + 64);
            v3 = __ldg(r + j + 96);
        } else {
            float s = (float)id * 1e-3f;
            v0 = sin4(s, j);
            v1 = sin4(s, j + 32);
            v2 = sin4(s, j + 64);
            v3 = sin4(s, j + 96);
        }

        float4* o = out + (size_t)t * DIM4;
        __stcs(o + j,      v0);
        __stcs(o + j + 32, v1);
        __stcs(o + j + 64, v2);
        __stcs(o + j + 96, v3);

        if (t_next >= n_tokens) break;
        t = t_next;
        id_cur = id_next;
    }
}

extern "C" void kernel_launch(void* const* d_in, const int* in_sizes, int n_in,
                              void* d_out, int out_size)
{
    // metadata order: x (int32), weight (float32), num_value (int32), is_num (bool)
    const int*    x = (const int*)d_in[0];
    const float4* w = (const float4*)d_in[1];
    float4*     out = (float4*)d_out;

    int n_tokens = in_sizes[0];           // 32768

    embed_kernel<<<GRID_BLOCKS, BLK_THREADS>>>(x, w, out, n_tokens);
}